// round 15
// baseline (speedup 1.0000x reference)
#include <cuda_runtime.h>
#include <cuda_fp16.h>
#include <cstdint>

#define NUM_TAGS 48
#define SEQ_LEN  512
#define BATCH    1024
#define CHUNK    8
#define NCHUNK   (SEQ_LEN / CHUNK)   // 64
#define KAPPA    4.4f                // per-step mass pre-scale (exact, compensated)

__device__ float    g_nll[BATCH];
__device__ unsigned g_count = 0;

__device__ __forceinline__ void cp16(uint32_t saddr, const void* g) {
    asm volatile("cp.async.cg.shared.global [%0], [%1], 16;" :: "r"(saddr), "l"(g));
}

// One warp (one CTA) per batch element. Alpha in shared as 48 fp16 (96 B, one
// 128-B line). Dot products via NATIVE __hfma2 (HFMA2, 2 MACs/instr, rt2).
// Emission factors pre-scaled by e^-KAPPA so fp16 state stays in range; the
// exact compensation KAPPA*n_applied is added to logZ. Lazy per-chunk renorm;
// fast path has no WARPSYNC (full-mask shfl anchors convergence).
__global__ __launch_bounds__(32)
void crf_fused_kernel(const float* __restrict__ emissions,
                      const float* __restrict__ transitions,
                      const int*   __restrict__ tags,
                      const int*   __restrict__ mask,
                      float*       __restrict__ out)
{
    const int lane = threadIdx.x;
    const int b    = blockIdx.x;
    const int h    = lane >> 4;     // K half: tags [24h, 24h+24)
    const int q    = lane & 15;     // owned output triple {3q,3q+1,3q+2}
    const int j0   = 3 * q;
    const float KINV = __expf(-KAPPA);

    __shared__ __align__(128) uint32_t swh[2][32];            // 48 fp16 + pad, x2 buffers
    __shared__ __align__(16)  float sem[3][CHUNK * NUM_TAGS]; // emission chunks
    __shared__ int stags[SEQ_LEN];
    __shared__ int smask[SEQ_LEN];

    const float* em_b   = emissions + (size_t)b * SEQ_LEN * NUM_TAGS;
    const int*   tags_b = tags + b * SEQ_LEN;
    const int*   mask_b = mask + b * SEQ_LEN;

    // --- stage emission chunks 0,1 --------------------------------------------
    #pragma unroll
    for (int pc = 0; pc < 2; pc++) {
        uint32_t dst = (uint32_t)__cvta_generic_to_shared(&sem[pc][0]);
        const float* src = em_b + (size_t)pc * CHUNK * NUM_TAGS;
        #pragma unroll
        for (int r = 0; r < 3; r++)
            cp16(dst + lane * 16 + r * 512, src + lane * 4 + r * 128);
        asm volatile("cp.async.commit_group;");
    }

    // --- tags / mask to shared ----------------------------------------------------
    #pragma unroll
    for (int r = 0; r < 4; r++) {
        ((int4*)stags)[lane + 32 * r] = ((const int4*)tags_b)[lane + 32 * r];
        ((int4*)smask)[lane + 32 * r] = ((const int4*)mask_b)[lane + 32 * r];
    }

    // --- E = exp(T) as half2: 3 owned cols x 12 input-pairs (this K half) ----------
    const int i0 = 24 * h;
    __half2 Ec[3][12];
    #pragma unroll
    for (int c = 0; c < 3; c++)
        #pragma unroll
        for (int k = 0; k < 12; k++)
            Ec[c][k] = __floats2half2_rn(
                __expf(transitions[(i0 + 2 * k    ) * NUM_TAGS + j0 + c]),
                __expf(transitions[(i0 + 2 * k + 1) * NUM_TAGS + j0 + c]));

    // --- init alphas: only tag 0 live (fp16(1.0)=0x3C00 in low half of word 0) -----
    float w0 = (q == 0) ? 1.0f : 0.0f;
    float w1 = 0.0f, w2 = 0.0f;
    if (lane < 24) swh[0][lane] = (lane == 0) ? 0x00003C00u : 0u;
    __syncwarp();

    // --- gold-path score (overlaps staged-chunk latency) ----------------------------
    float sc = 0.0f;
    #pragma unroll 4
    for (int t = 1 + lane; t < SEQ_LEN; t += 32) {
        int tc = stags[t], tp = stags[t - 1];
        if (smask[t])
            sc += em_b[(size_t)t * NUM_TAGS + tc] + transitions[tp * NUM_TAGS + tc];
    }
    #pragma unroll
    for (int off = 16; off; off >>= 1)
        sc += __shfl_xor_sync(0xffffffffu, sc, off);

    // --- forward recursion: 64 chunks x 8 steps --------------------------------------
    float C = 0.0f;          // accumulated log-scale of stored state
    float carry_inv = 1.0f;  // pending renorm scale (exact once logged)
    int   nk = 0;            // number of steps where the KINV factor was applied

    for (int c = 0; c < NCHUNK; c++) {
        if (c + 2 < NCHUNK) {
            uint32_t dst = (uint32_t)__cvta_generic_to_shared(&sem[(c + 2) % 3][0]);
            const float* src = em_b + (size_t)(c + 2) * CHUNK * NUM_TAGS;
            #pragma unroll
            for (int r = 0; r < 3; r++)
                cp16(dst + lane * 16 + r * 512, src + lane * 4 + r * 128);
        }
        asm volatile("cp.async.commit_group;");
        asm volatile("cp.async.wait_group 2;");
        __syncwarp();

        const float* eb = sem[c % 3];

        // hoist emission exps (pre-scaled by KINV; off the recurrence chain)
        float eE[CHUNK][3];
        #pragma unroll
        for (int u = 0; u < CHUNK; u++) {
            eE[u][0] = __expf(eb[u * NUM_TAGS + j0])     * KINV;
            eE[u][1] = __expf(eb[u * NUM_TAGS + j0 + 1]) * KINV;
            eE[u][2] = __expf(eb[u * NUM_TAGS + j0 + 2]) * KINV;
        }

        const int4 ma  = ((const int4*)(smask + c * CHUNK))[0];
        const int4 mbq = ((const int4*)(smask + c * CHUNK))[1];
        const int mall = ma.x & ma.y & ma.z & ma.w & mbq.x & mbq.y & mbq.z & mbq.w;

        if (mall) {
            // fast path: fold pending scale into step 0's emission factor
            eE[0][0] *= carry_inv; eE[0][1] *= carry_inv; eE[0][2] *= carry_inv;
            nk += CHUNK;

            #pragma unroll
            for (int u = 0; u < CHUNK; u++) {
                // alpha: this half's 24 fp16 = 48 B = 3 LDS.128 (one 128-B line)
                const uint32_t* wln = &swh[u & 1][h * 12];
                uint4 A0 = *(const uint4*)(wln);
                uint4 A1 = *(const uint4*)(wln + 4);
                uint4 A2 = *(const uint4*)(wln + 8);
                uint32_t A[12] = {A0.x, A0.y, A0.z, A0.w,
                                  A1.x, A1.y, A1.z, A1.w,
                                  A2.x, A2.y, A2.z, A2.w};
                const __half2* Ah = (const __half2*)A;

                // native HFMA2 dots: 2 chains x 6 per column
                __half2 pa[3], pb[3];
                #pragma unroll
                for (int cc = 0; cc < 3; cc++) {
                    pa[cc] = __float2half2_rn(0.0f);
                    pb[cc] = __float2half2_rn(0.0f);
                }
                #pragma unroll
                for (int k = 0; k < 6; k++) {
                    #pragma unroll
                    for (int cc = 0; cc < 3; cc++) {
                        pa[cc] = __hfma2(Ah[k],     Ec[cc][k],     pa[cc]);
                        pb[cc] = __hfma2(Ah[k + 6], Ec[cc][k + 6], pb[cc]);
                    }
                }
                float d[3];
                #pragma unroll
                for (int cc = 0; cc < 3; cc++) {
                    __half2 s2 = __hadd2(pa[cc], pb[cc]);
                    float dd = __low2float(s2) + __high2float(s2);
                    dd += __shfl_xor_sync(0xffffffffu, dd, 16);   // combine K halves
                    d[cc] = dd * eE[u][cc];
                }
                w0 = d[0]; w1 = d[1]; w2 = d[2];
                __half* wd = (__half*)swh[(u & 1) ^ 1];
                wd[j0]     = __float2half(w0);   // all lanes store; pair duplicates identical
                wd[j0 + 1] = __float2half(w1);
                wd[j0 + 2] = __float2half(w2);
                asm volatile("" ::: "memory");
            }
        } else {
            // slow path (general mask): apply pending scale, then select-based steps
            w0 *= carry_inv; w1 *= carry_inv; w2 *= carry_inv;
            carry_inv = 1.0f;
            {
                __half* wd = (__half*)swh[0];
                wd[j0]     = __float2half(w0);
                wd[j0 + 1] = __float2half(w1);
                wd[j0 + 2] = __float2half(w2);
            }
            __syncwarp();

            #pragma unroll
            for (int u = 0; u < CHUNK; u++) {
                const uint32_t* wln = &swh[u & 1][h * 12];
                uint4 A0 = *(const uint4*)(wln);
                uint4 A1 = *(const uint4*)(wln + 4);
                uint4 A2 = *(const uint4*)(wln + 8);
                uint32_t A[12] = {A0.x, A0.y, A0.z, A0.w,
                                  A1.x, A1.y, A1.z, A1.w,
                                  A2.x, A2.y, A2.z, A2.w};
                const __half2* Ah = (const __half2*)A;

                __half2 pa[3], pb[3];
                #pragma unroll
                for (int cc = 0; cc < 3; cc++) {
                    pa[cc] = __float2half2_rn(0.0f);
                    pb[cc] = __float2half2_rn(0.0f);
                }
                #pragma unroll
                for (int k = 0; k < 6; k++) {
                    #pragma unroll
                    for (int cc = 0; cc < 3; cc++) {
                        pa[cc] = __hfma2(Ah[k],     Ec[cc][k],     pa[cc]);
                        pb[cc] = __hfma2(Ah[k + 6], Ec[cc][k + 6], pb[cc]);
                    }
                }
                int m = smask[c * CHUNK + u];
                nk += (m ? 1 : 0);
                float nv[3];
                #pragma unroll
                for (int cc = 0; cc < 3; cc++) {
                    __half2 s2 = __hadd2(pa[cc], pb[cc]);
                    float dd = __low2float(s2) + __high2float(s2);
                    dd += __shfl_xor_sync(0xffffffffu, dd, 16);
                    nv[cc] = dd * eE[u][cc];
                }
                w0 = m ? nv[0] : w0;
                w1 = m ? nv[1] : w1;
                w2 = m ? nv[2] : w2;
                __half* wd = (__half*)swh[(u & 1) ^ 1];
                wd[j0]     = __float2half(w0);
                wd[j0 + 1] = __float2half(w1);
                wd[j0 + 2] = __float2half(w2);
                __syncwarp();
            }
        }

        // lazy renorm: scale by alpha[0] (>0 always); exact algebra once logged
        float s = __shfl_sync(0xffffffffu, w0, 0);
        C += __logf(s);
        carry_inv = __fdividef(1.0f, s);
    }

    // --- final: logZ = C + log((sum w)*carry_inv) + KAPPA*nk -------------------------
    float v = (h == 0) ? (w0 + w1 + w2) : 0.0f;
    #pragma unroll
    for (int off = 16; off; off >>= 1)
        v += __shfl_xor_sync(0xffffffffu, v, off);
    if (lane == 0) {
        float logZ  = C + __logf(v * carry_inv) + KAPPA * (float)nk;
        float score = sc + em_b[stags[0]];           // emit[0] always counted
        g_nll[b] = logZ - score;
    }

    // --- fused mean-reduce: last CTA does the deterministic sum ----------------------
    unsigned done = 0;
    if (lane == 0) {
        __threadfence();
        done = atomicAdd(&g_count, 1u);
    }
    done = __shfl_sync(0xffffffffu, done, 0);
    if (done == BATCH - 1) {
        __threadfence();
        float r = 0.0f;
        #pragma unroll
        for (int i = lane; i < BATCH; i += 32)
            r += __ldcg(&g_nll[i]);
        #pragma unroll
        for (int off = 16; off; off >>= 1)
            r += __shfl_xor_sync(0xffffffffu, r, off);
        if (lane == 0) {
            out[0] = r * (1.0f / (float)BATCH);
            g_count = 0;   // reset for next graph replay
        }
    }
}

extern "C" void kernel_launch(void* const* d_in, const int* in_sizes, int n_in,
                              void* d_out, int out_size)
{
    const float* emissions   = (const float*)d_in[0];
    const float* transitions = (const float*)d_in[1];
    const int*   tags        = (const int*)d_in[2];
    const int*   mask        = (const int*)d_in[3];
    float*       out         = (float*)d_out;

    crf_fused_kernel<<<BATCH, 32>>>(emissions, transitions, tags, mask, out);
}

// round 16
// speedup vs baseline: 1.0027x; 1.0027x over previous
#include <cuda_runtime.h>
#include <cuda_bf16.h>
#include <cstdint>

#define NUM_TAGS 48
#define SEQ_LEN  512
#define BATCH    1024
#define CHUNK    8
#define NCH      32                  // chunks per chain (256 steps each)

__device__ float    g_nll[BATCH];
__device__ unsigned g_count = 0;

// ---- packed f32x2 helpers ------------------------------------------------------
__device__ __forceinline__ void fma2(uint64_t& d, uint64_t a, uint64_t b) {
    asm("fma.rn.f32x2 %0, %1, %2, %0;" : "+l"(d) : "l"(a), "l"(b));
}
__device__ __forceinline__ uint64_t add2(uint64_t a, uint64_t b) {
    uint64_t d;
    asm("add.rn.f32x2 %0, %1, %2;" : "=l"(d) : "l"(a), "l"(b));
    return d;
}
__device__ __forceinline__ uint64_t pack2(float lo, float hi) {
    uint64_t d;
    asm("mov.b64 %0, {%1, %2};" : "=l"(d) : "f"(lo), "f"(hi));
    return d;
}
__device__ __forceinline__ float lo2(uint64_t v) { return __uint_as_float((uint32_t)v); }
__device__ __forceinline__ float hi2(uint64_t v) { return __uint_as_float((uint32_t)(v >> 32)); }

__device__ __forceinline__ void cp16(uint32_t saddr, const void* g) {
    asm volatile("cp.async.cg.shared.global [%0], [%1], 16;" :: "r"(saddr), "l"(g));
}

// One warp (one CTA) per batch element, running TWO independent recurrence
// chains interleaved: forward over t=[0,256) and backward (transpose) over
// t=[256,512). Exact: logZ = C_f + C_b + log(w_hat . v_hat).
__global__ __launch_bounds__(32)
void crf_dual_kernel(const float* __restrict__ emissions,
                     const float* __restrict__ transitions,
                     const int*   __restrict__ tags,
                     const int*   __restrict__ mask,
                     float*       __restrict__ out)
{
    const int lane = threadIdx.x;
    const int b    = blockIdx.x;
    const int h    = lane >> 4;     // K half: [24h, 24h+24)
    const int q    = lane & 15;     // owned triple {3q..3q+2}
    const int j0   = 3 * q;
    const int i0   = 24 * h;

    __shared__ __align__(16) float swF[2][NUM_TAGS];       // fwd alpha ping-pong
    __shared__ __align__(16) float swB[2][NUM_TAGS];       // bwd y ping-pong
    __shared__ __align__(16) float semF[3][CHUNK * NUM_TAGS];
    __shared__ __align__(16) float semB[3][CHUNK * NUM_TAGS];
    __shared__ int stags[SEQ_LEN];
    __shared__ int smask[SEQ_LEN];

    const float* em_b   = emissions + (size_t)b * SEQ_LEN * NUM_TAGS;
    const int*   tags_b = tags + b * SEQ_LEN;
    const int*   mask_b = mask + b * SEQ_LEN;

    #define TBB(c) (SEQ_LEN - CHUNK * ((c) + 1))   // bwd chunk base t

    // --- stage chunks 0,1 of BOTH streams ----------------------------------------
    #pragma unroll
    for (int pc = 0; pc < 2; pc++) {
        uint32_t dF = (uint32_t)__cvta_generic_to_shared(&semF[pc][0]);
        uint32_t dB = (uint32_t)__cvta_generic_to_shared(&semB[pc][0]);
        const float* sF = em_b + (size_t)pc * CHUNK * NUM_TAGS;
        const float* sB = em_b + (size_t)TBB(pc) * NUM_TAGS;
        #pragma unroll
        for (int r = 0; r < 3; r++) {
            cp16(dF + lane * 16 + r * 512, sF + lane * 4 + r * 128);
            cp16(dB + lane * 16 + r * 512, sB + lane * 4 + r * 128);
        }
        asm volatile("cp.async.commit_group;");
    }

    // --- tags / mask to shared -----------------------------------------------------
    #pragma unroll
    for (int r = 0; r < 4; r++) {
        ((int4*)stags)[lane + 32 * r] = ((const int4*)tags_b)[lane + 32 * r];
        ((int4*)smask)[lane + 32 * r] = ((const int4*)mask_b)[lane + 32 * r];
    }

    // --- E registers: fwd columns (Ec) and bwd rows (Er), f32x2-packed ---------------
    uint64_t Ec[36], Er[36];
    #pragma unroll
    for (int cc = 0; cc < 3; cc++)
        #pragma unroll
        for (int k = 0; k < 12; k++) {
            Ec[cc * 12 + k] = pack2(__expf(transitions[(i0 + 2 * k    ) * NUM_TAGS + j0 + cc]),
                                    __expf(transitions[(i0 + 2 * k + 1) * NUM_TAGS + j0 + cc]));
            Er[cc * 12 + k] = pack2(__expf(transitions[(j0 + cc) * NUM_TAGS + i0 + 2 * k    ]),
                                    __expf(transitions[(j0 + cc) * NUM_TAGS + i0 + 2 * k + 1]));
        }

    // --- init fwd state: only tag 0 live ----------------------------------------------
    float w0 = (q == 0) ? 1.0f : 0.0f, w1 = 0.0f, w2 = 0.0f;
    swF[0][j0] = w0; swF[0][j0 + 1] = w1; swF[0][j0 + 2] = w2;
    float v0 = 1.0f, v1 = 1.0f, v2 = 1.0f;   // bwd v
    __syncwarp();

    // --- gold-path score (full range; overlaps staging) --------------------------------
    float sc = 0.0f;
    #pragma unroll 4
    for (int t = 1 + lane; t < SEQ_LEN; t += 32) {
        int tc = stags[t], tp = stags[t - 1];
        if (smask[t])
            sc += em_b[(size_t)t * NUM_TAGS + tc] + transitions[tp * NUM_TAGS + tc];
    }
    #pragma unroll
    for (int off = 16; off; off >>= 1)
        sc += __shfl_xor_sync(0xffffffffu, sc, off);

    // --- dual recursion: 32 chunks x 8 steps each chain ---------------------------------
    float CF = 0.0f, carryF = 1.0f;   // fwd lazy renorm
    float CB = 0.0f;                  // bwd renorm applied at chunk end (no pending)

    for (int c = 0; c < NCH; c++) {
        const int tbB = TBB(c);

        // boundary emission for bwd store-scale at its last step (t = tbB-1)
        float eP0 = __expf(__ldg(em_b + (size_t)(tbB - 1) * NUM_TAGS + j0));
        float eP1 = __expf(__ldg(em_b + (size_t)(tbB - 1) * NUM_TAGS + j0 + 1));
        float eP2 = __expf(__ldg(em_b + (size_t)(tbB - 1) * NUM_TAGS + j0 + 2));

        if (c + 2 < NCH) {
            uint32_t dF = (uint32_t)__cvta_generic_to_shared(&semF[(c + 2) % 3][0]);
            uint32_t dB = (uint32_t)__cvta_generic_to_shared(&semB[(c + 2) % 3][0]);
            const float* sF = em_b + (size_t)(c + 2) * CHUNK * NUM_TAGS;
            const float* sB = em_b + (size_t)TBB(c + 2) * NUM_TAGS;
            #pragma unroll
            for (int r = 0; r < 3; r++) {
                cp16(dF + lane * 16 + r * 512, sF + lane * 4 + r * 128);
                cp16(dB + lane * 16 + r * 512, sB + lane * 4 + r * 128);
            }
        }
        asm volatile("cp.async.commit_group;");
        asm volatile("cp.async.wait_group 2;");
        __syncwarp();

        const float* ebF = semF[c % 3];
        const float* ebB = semB[c % 3];

        if (c == 0) {   // init bwd y_511 = exp(e_511) . 1
            swB[0][j0]     = __expf(ebB[7 * NUM_TAGS + j0]);
            swB[0][j0 + 1] = __expf(ebB[7 * NUM_TAGS + j0 + 1]);
            swB[0][j0 + 2] = __expf(ebB[7 * NUM_TAGS + j0 + 2]);
            __syncwarp();
        }

        const int4 fa = ((const int4*)(smask + c * CHUNK))[0];
        const int4 fb = ((const int4*)(smask + c * CHUNK))[1];
        const int4 ba = ((const int4*)(smask + tbB))[0];
        const int4 bb = ((const int4*)(smask + tbB))[1];
        const int mall = fa.x & fa.y & fa.z & fa.w & fb.x & fb.y & fb.z & fb.w
                       & ba.x & ba.y & ba.z & ba.w & bb.x & bb.y & bb.z & bb.w;

        if (mall) {
            #pragma unroll
            for (int u = 0; u < CHUNK; u++) {
                // ----- emission scales (independent of state chains) -------------
                float eF0 = __expf(ebF[u * NUM_TAGS + j0]);
                float eF1 = __expf(ebF[u * NUM_TAGS + j0 + 1]);
                float eF2 = __expf(ebF[u * NUM_TAGS + j0 + 2]);
                if (u == 0) { eF0 *= carryF; eF1 *= carryF; eF2 *= carryF; }
                const int tprev = 6 - u;   // bwd store-scale row (u'=7-u, t-1 = tbB+6-u)
                float sB0 = (u < 7) ? __expf(ebB[tprev * NUM_TAGS + j0])     : eP0;
                float sB1 = (u < 7) ? __expf(ebB[tprev * NUM_TAGS + j0 + 1]) : eP1;
                float sB2 = (u < 7) ? __expf(ebB[tprev * NUM_TAGS + j0 + 2]) : eP2;

                // ----- dual FMA chains (independent; ptxas interleaves) ----------
                const ulonglong2* wv = (const ulonglong2*)(&swF[u & 1][i0]);
                const ulonglong2* yv = (const ulonglong2*)(&swB[u & 1][i0]);
                uint64_t f0[3] = {0,0,0}, f1[3] = {0,0,0};
                uint64_t g0[3] = {0,0,0}, g1[3] = {0,0,0};
                #pragma unroll
                for (int r = 0; r < 6; r++) {
                    ulonglong2 W = wv[r];
                    ulonglong2 Y = yv[r];
                    #pragma unroll
                    for (int cc = 0; cc < 3; cc++) {
                        fma2(f0[cc], W.x, Ec[cc * 12 + 2 * r]);
                        fma2(f1[cc], W.y, Ec[cc * 12 + 2 * r + 1]);
                        fma2(g0[cc], Y.x, Er[cc * 12 + 2 * r]);
                        fma2(g1[cc], Y.y, Er[cc * 12 + 2 * r + 1]);
                    }
                }
                // fwd combine + store
                {
                    uint64_t s0 = add2(f0[0], f1[0]);
                    uint64_t s1 = add2(f0[1], f1[1]);
                    uint64_t s2 = add2(f0[2], f1[2]);
                    float d0 = lo2(s0) + hi2(s0);
                    float d1 = lo2(s1) + hi2(s1);
                    float d2 = lo2(s2) + hi2(s2);
                    d0 += __shfl_xor_sync(0xffffffffu, d0, 16);
                    d1 += __shfl_xor_sync(0xffffffffu, d1, 16);
                    d2 += __shfl_xor_sync(0xffffffffu, d2, 16);
                    w0 = d0 * eF0; w1 = d1 * eF1; w2 = d2 * eF2;
                    float* wd = swF[(u & 1) ^ 1];
                    wd[j0] = w0; wd[j0 + 1] = w1; wd[j0 + 2] = w2;
                }
                // bwd combine + scaled store
                {
                    uint64_t s0 = add2(g0[0], g1[0]);
                    uint64_t s1 = add2(g0[1], g1[1]);
                    uint64_t s2 = add2(g0[2], g1[2]);
                    float d0 = lo2(s0) + hi2(s0);
                    float d1 = lo2(s1) + hi2(s1);
                    float d2 = lo2(s2) + hi2(s2);
                    d0 += __shfl_xor_sync(0xffffffffu, d0, 16);
                    d1 += __shfl_xor_sync(0xffffffffu, d1, 16);
                    d2 += __shfl_xor_sync(0xffffffffu, d2, 16);
                    v0 = d0; v1 = d1; v2 = d2;
                    float* yd = swB[(u & 1) ^ 1];
                    yd[j0] = sB0 * v0; yd[j0 + 1] = sB1 * v1; yd[j0 + 2] = sB2 * v2;
                }
                asm volatile("" ::: "memory");
            }
        } else {
            // ---------------- slow path: sequential, per-step masks -----------------
            // fwd: materialize pending carry first
            w0 *= carryF; w1 *= carryF; w2 *= carryF;
            carryF = 1.0f;
            swF[0][j0] = w0; swF[0][j0 + 1] = w1; swF[0][j0 + 2] = w2;
            __syncwarp();
            #pragma unroll
            for (int u = 0; u < CHUNK; u++) {
                const ulonglong2* wv = (const ulonglong2*)(&swF[u & 1][i0]);
                uint64_t f0[3] = {0,0,0}, f1[3] = {0,0,0};
                #pragma unroll
                for (int r = 0; r < 6; r++) {
                    ulonglong2 W = wv[r];
                    #pragma unroll
                    for (int cc = 0; cc < 3; cc++) {
                        fma2(f0[cc], W.x, Ec[cc * 12 + 2 * r]);
                        fma2(f1[cc], W.y, Ec[cc * 12 + 2 * r + 1]);
                    }
                }
                int m = smask[c * CHUNK + u];
                float nv[3];
                #pragma unroll
                for (int cc = 0; cc < 3; cc++) {
                    uint64_t s = add2(f0[cc], f1[cc]);
                    float dd = lo2(s) + hi2(s);
                    dd += __shfl_xor_sync(0xffffffffu, dd, 16);
                    nv[cc] = dd * __expf(ebF[u * NUM_TAGS + j0 + cc]);
                }
                w0 = m ? nv[0] : w0;
                w1 = m ? nv[1] : w1;
                w2 = m ? nv[2] : w2;
                float* wd = swF[(u & 1) ^ 1];
                wd[j0] = w0; wd[j0 + 1] = w1; wd[j0 + 2] = w2;
                __syncwarp();
            }
            // bwd
            #pragma unroll
            for (int u = 0; u < CHUNK; u++) {
                const ulonglong2* yv = (const ulonglong2*)(&swB[u & 1][i0]);
                uint64_t g0[3] = {0,0,0}, g1[3] = {0,0,0};
                #pragma unroll
                for (int r = 0; r < 6; r++) {
                    ulonglong2 Y = yv[r];
                    #pragma unroll
                    for (int cc = 0; cc < 3; cc++) {
                        fma2(g0[cc], Y.x, Er[cc * 12 + 2 * r]);
                        fma2(g1[cc], Y.y, Er[cc * 12 + 2 * r + 1]);
                    }
                }
                int m = smask[tbB + 7 - u];
                float nv[3];
                #pragma unroll
                for (int cc = 0; cc < 3; cc++) {
                    uint64_t s = add2(g0[cc], g1[cc]);
                    float dd = lo2(s) + hi2(s);
                    dd += __shfl_xor_sync(0xffffffffu, dd, 16);
                    nv[cc] = dd;
                }
                v0 = m ? nv[0] : v0;
                v1 = m ? nv[1] : v1;
                v2 = m ? nv[2] : v2;
                const int tprev = 6 - u;
                float s0 = (u < 7) ? __expf(ebB[tprev * NUM_TAGS + j0])     : eP0;
                float s1 = (u < 7) ? __expf(ebB[tprev * NUM_TAGS + j0 + 1]) : eP1;
                float s2 = (u < 7) ? __expf(ebB[tprev * NUM_TAGS + j0 + 2]) : eP2;
                float* yd = swB[(u & 1) ^ 1];
                yd[j0] = s0 * v0; yd[j0 + 1] = s1 * v1; yd[j0 + 2] = s2 * v2;
                __syncwarp();
            }
        }

        // --- renorm both chains (exact once logged) ---------------------------------
        float sF = __shfl_sync(0xffffffffu, w0, 0);     // > 0
        CF += __logf(sF);
        carryF = __fdividef(1.0f, sF);

        float sB = __shfl_sync(0xffffffffu, v0, 0);     // > 0
        CB += __logf(sB);
        float cb = __fdividef(1.0f, sB);
        v0 *= cb; v1 *= cb; v2 *= cb;
        // rewrite stored y (buffer 0 after 8 steps) consistently with normalized v
        swB[0][j0]     = eP0 * v0;
        swB[0][j0 + 1] = eP1 * v1;
        swB[0][j0 + 2] = eP2 * v2;
        __syncwarp();
    }

    // --- combine: logZ = CF + CB + log( (w . v) * carryF ) ----------------------------
    float d = (h == 0) ? (w0 * v0 + w1 * v1 + w2 * v2) : 0.0f;
    #pragma unroll
    for (int off = 16; off; off >>= 1)
        d += __shfl_xor_sync(0xffffffffu, d, off);
    if (lane == 0) {
        float logZ  = CF + CB + __logf(d * carryF);
        float score = sc + em_b[stags[0]];            // emit[0] always counted
        g_nll[b] = logZ - score;
    }

    // --- fused mean-reduce: last CTA does the deterministic sum ------------------------
    unsigned done = 0;
    if (lane == 0) {
        __threadfence();
        done = atomicAdd(&g_count, 1u);
    }
    done = __shfl_sync(0xffffffffu, done, 0);
    if (done == BATCH - 1) {
        __threadfence();
        float r = 0.0f;
        #pragma unroll
        for (int i = lane; i < BATCH; i += 32)
            r += __ldcg(&g_nll[i]);
        #pragma unroll
        for (int off = 16; off; off >>= 1)
            r += __shfl_xor_sync(0xffffffffu, r, off);
        if (lane == 0) {
            out[0] = r * (1.0f / (float)BATCH);
            g_count = 0;   // reset for next graph replay
        }
    }
    #undef TBB
}

extern "C" void kernel_launch(void* const* d_in, const int* in_sizes, int n_in,
                              void* d_out, int out_size)
{
    const float* emissions   = (const float*)d_in[0];
    const float* transitions = (const float*)d_in[1];
    const int*   tags        = (const int*)d_in[2];
    const int*   mask        = (const int*)d_in[3];
    float*       out         = (float*)d_out;

    crf_dual_kernel<<<BATCH, 32>>>(emissions, transitions, tags, mask, out);
}

// round 17
// speedup vs baseline: 1.0810x; 1.0782x over previous
#include <cuda_runtime.h>
#include <cuda_bf16.h>
#include <cstdint>

#define NUM_TAGS 48
#define SEQ_LEN  512
#define BATCH    1024
#define CHUNK    16
#define NCHUNK   (SEQ_LEN / CHUNK)   // 32

__device__ float    g_nll[BATCH];
__device__ unsigned g_count = 0;

// ---- packed f32x2 helpers (Blackwell packed-FMA path, PTX-only) ---------------
__device__ __forceinline__ void fma2(uint64_t& d, uint64_t a, uint64_t b) {
    asm("fma.rn.f32x2 %0, %1, %2, %0;" : "+l"(d) : "l"(a), "l"(b));
}
__device__ __forceinline__ uint64_t add2(uint64_t a, uint64_t b) {
    uint64_t d;
    asm("add.rn.f32x2 %0, %1, %2;" : "=l"(d) : "l"(a), "l"(b));
    return d;
}
__device__ __forceinline__ uint64_t pack2(float lo, float hi) {
    uint64_t d;
    asm("mov.b64 %0, {%1, %2};" : "=l"(d) : "f"(lo), "f"(hi));
    return d;
}
__device__ __forceinline__ float lo2(uint64_t v) { return __uint_as_float((uint32_t)v); }
__device__ __forceinline__ float hi2(uint64_t v) { return __uint_as_float((uint32_t)(v >> 32)); }

__device__ __forceinline__ void cp16(uint32_t saddr, const void* g) {
    asm volatile("cp.async.cg.shared.global [%0], [%1], 16;" :: "r"(saddr), "l"(g));
}

// One warp (one CTA) per batch element. R7 structure with CHUNK=16:
// half the chunk boundaries (wait/sync/renorm), renorm every 16 steps (safe:
// worst-case growth ~1e32 << fp32 max), emission exps hoisted in two groups
// of 8 to cap register pressure. Fast path has no WARPSYNC (full-mask shfl
// anchors convergence; pair lanes store bit-identical duplicates).
__global__ __launch_bounds__(32)
void crf_fused_kernel(const float* __restrict__ emissions,
                      const float* __restrict__ transitions,
                      const int*   __restrict__ tags,
                      const int*   __restrict__ mask,
                      float*       __restrict__ out)
{
    const int lane = threadIdx.x;
    const int b    = blockIdx.x;
    const int h    = lane >> 4;     // K half: tags [24h, 24h+24)
    const int q    = lane & 15;     // owned output triple {3q,3q+1,3q+2}
    const int j0   = 3 * q;
    const int i0   = 24 * h;

    __shared__ __align__(16) float swbuf[2][NUM_TAGS];        // alpha ping-pong
    __shared__ __align__(16) float sem[2][CHUNK * NUM_TAGS];  // emission chunks
    __shared__ int stags[SEQ_LEN];
    __shared__ int smask[SEQ_LEN];

    const float* em_b   = emissions + (size_t)b * SEQ_LEN * NUM_TAGS;
    const int*   tags_b = tags + b * SEQ_LEN;
    const int*   mask_b = mask + b * SEQ_LEN;

    // --- stage emission chunk 0 (16 steps = 3KB, 6 cp16/lane) -------------------
    {
        uint32_t dst = (uint32_t)__cvta_generic_to_shared(&sem[0][0]);
        #pragma unroll
        for (int r = 0; r < 6; r++)
            cp16(dst + lane * 16 + r * 512, em_b + lane * 4 + r * 128);
        asm volatile("cp.async.commit_group;");
    }

    // --- tags / mask to shared ------------------------------------------------------
    #pragma unroll
    for (int r = 0; r < 4; r++) {
        ((int4*)stags)[lane + 32 * r] = ((const int4*)tags_b)[lane + 32 * r];
        ((int4*)smask)[lane + 32 * r] = ((const int4*)mask_b)[lane + 32 * r];
    }

    // --- E = exp(T): half-column slices, 3 output cols per lane ----------------------
    uint64_t Ec[36];
    #pragma unroll
    for (int c = 0; c < 3; c++)
        #pragma unroll
        for (int k = 0; k < 12; k++)
            Ec[c * 12 + k] = pack2(__expf(transitions[(i0 + 2 * k    ) * NUM_TAGS + j0 + c]),
                                   __expf(transitions[(i0 + 2 * k + 1) * NUM_TAGS + j0 + c]));

    // --- init alphas (linear): only tag 0 live ----------------------------------------
    float w0 = (q == 0) ? 1.0f : 0.0f;
    float w1 = 0.0f, w2 = 0.0f;
    swbuf[0][j0]     = w0;    // all lanes store (q / q+16 duplicates identical)
    swbuf[0][j0 + 1] = w1;
    swbuf[0][j0 + 2] = w2;
    __syncwarp();

    // --- gold-path score (overlaps staged chunk-0 latency) -----------------------------
    float sc = 0.0f;
    #pragma unroll 4
    for (int t = 1 + lane; t < SEQ_LEN; t += 32) {
        int tc = stags[t], tp = stags[t - 1];
        if (smask[t])
            sc += em_b[(size_t)t * NUM_TAGS + tc] + transitions[tp * NUM_TAGS + tc];
    }
    #pragma unroll
    for (int off = 16; off; off >>= 1)
        sc += __shfl_xor_sync(0xffffffffu, sc, off);

    // --- forward recursion: 32 chunks x 16 steps -----------------------------------------
    float C = 0.0f;
    float carry_inv = 1.0f;   // pending renorm scale (exact once logged)

    for (int c = 0; c < NCHUNK; c++) {
        if (c + 1 < NCHUNK) {
            uint32_t dst = (uint32_t)__cvta_generic_to_shared(&sem[(c + 1) & 1][0]);
            const float* src = em_b + (size_t)(c + 1) * CHUNK * NUM_TAGS;
            #pragma unroll
            for (int r = 0; r < 6; r++)
                cp16(dst + lane * 16 + r * 512, src + lane * 4 + r * 128);
        }
        asm volatile("cp.async.commit_group;");
        asm volatile("cp.async.wait_group 1;");   // chunk c resident
        __syncwarp();

        const float* eb = sem[c & 1];

        // uniform mask test for this chunk (16 values)
        const int4 m0v = ((const int4*)(smask + c * CHUNK))[0];
        const int4 m1v = ((const int4*)(smask + c * CHUNK))[1];
        const int4 m2v = ((const int4*)(smask + c * CHUNK))[2];
        const int4 m3v = ((const int4*)(smask + c * CHUNK))[3];
        const int mall = m0v.x & m0v.y & m0v.z & m0v.w & m1v.x & m1v.y & m1v.z & m1v.w
                       & m2v.x & m2v.y & m2v.z & m2v.w & m3v.x & m3v.y & m3v.z & m3v.w;

        if (mall) {
            // fast path: two sub-groups of 8 steps (exps hoisted per sub-group)
            #pragma unroll
            for (int gsub = 0; gsub < 2; gsub++) {
                float eE[8][3];
                #pragma unroll
                for (int u = 0; u < 8; u++) {
                    const float* ep = eb + (gsub * 8 + u) * NUM_TAGS + j0;
                    eE[u][0] = __expf(ep[0]);
                    eE[u][1] = __expf(ep[1]);
                    eE[u][2] = __expf(ep[2]);
                }
                if (gsub == 0) {   // fold pending renorm scale into step 0
                    eE[0][0] *= carry_inv; eE[0][1] *= carry_inv; eE[0][2] *= carry_inv;
                }
                #pragma unroll
                for (int u = 0; u < 8; u++) {
                    const ulonglong2* wv = (const ulonglong2*)(&swbuf[u & 1][i0]);
                    uint64_t a0[3] = {0,0,0}, a1[3] = {0,0,0};
                    #pragma unroll
                    for (int r = 0; r < 6; r++) {
                        ulonglong2 W = wv[r];
                        #pragma unroll
                        for (int cc = 0; cc < 3; cc++) {
                            fma2(a0[cc], W.x, Ec[cc * 12 + 2 * r]);
                            fma2(a1[cc], W.y, Ec[cc * 12 + 2 * r + 1]);
                        }
                    }
                    float* wd = swbuf[(u & 1) ^ 1];
                    #pragma unroll
                    for (int cc = 0; cc < 3; cc++) {
                        uint64_t s = add2(a0[cc], a1[cc]);
                        float d = lo2(s) + hi2(s);                  // own half-dot
                        d += __shfl_xor_sync(0xffffffffu, d, 16);   // symmetric combine
                        d *= eE[u][cc];                             // pair-identical
                        if (cc == 0) w0 = d; else if (cc == 1) w1 = d; else w2 = d;
                        wd[j0 + cc] = d;                            // all lanes store
                    }
                    asm volatile("" ::: "memory");
                }
            }
        } else {
            // slow path (general mask): apply pending scale, then select-based steps
            w0 *= carry_inv; w1 *= carry_inv; w2 *= carry_inv;
            carry_inv = 1.0f;
            swbuf[0][j0] = w0; swbuf[0][j0 + 1] = w1; swbuf[0][j0 + 2] = w2;
            __syncwarp();

            #pragma unroll
            for (int u = 0; u < CHUNK; u++) {
                const ulonglong2* wv = (const ulonglong2*)(&swbuf[u & 1][i0]);
                uint64_t a0[3] = {0,0,0}, a1[3] = {0,0,0};
                #pragma unroll
                for (int r = 0; r < 6; r++) {
                    ulonglong2 W = wv[r];
                    #pragma unroll
                    for (int cc = 0; cc < 3; cc++) {
                        fma2(a0[cc], W.x, Ec[cc * 12 + 2 * r]);
                        fma2(a1[cc], W.y, Ec[cc * 12 + 2 * r + 1]);
                    }
                }
                int m = smask[c * CHUNK + u];
                float nv[3];
                #pragma unroll
                for (int cc = 0; cc < 3; cc++) {
                    uint64_t s = add2(a0[cc], a1[cc]);
                    float d = lo2(s) + hi2(s);
                    d += __shfl_xor_sync(0xffffffffu, d, 16);
                    nv[cc] = d * __expf(eb[u * NUM_TAGS + j0 + cc]);
                }
                w0 = m ? nv[0] : w0;
                w1 = m ? nv[1] : w1;
                w2 = m ? nv[2] : w2;
                float* wd = swbuf[(u & 1) ^ 1];
                wd[j0] = w0; wd[j0 + 1] = w1; wd[j0 + 2] = w2;
                __syncwarp();
            }
        }

        // lazy renorm every 16 steps: scale by alpha[0] (>0); exact once logged
        float s = __shfl_sync(0xffffffffu, w0, 0);
        C += __logf(s);
        carry_inv = __fdividef(1.0f, s);
    }

    // --- final partition: logZ = C + log( (sum w) * carry_inv ) -------------------------
    float v = (h == 0) ? (w0 + w1 + w2) : 0.0f;
    #pragma unroll
    for (int off = 16; off; off >>= 1)
        v += __shfl_xor_sync(0xffffffffu, v, off);
    if (lane == 0) {
        float logZ  = C + __logf(v * carry_inv);
        float score = sc + em_b[stags[0]];           // emit[0] always counted
        g_nll[b] = logZ - score;
    }

    // --- fused mean-reduce: last CTA does the deterministic sum --------------------------
    unsigned done = 0;
    if (lane == 0) {
        __threadfence();
        done = atomicAdd(&g_count, 1u);
    }
    done = __shfl_sync(0xffffffffu, done, 0);
    if (done == BATCH - 1) {
        __threadfence();
        float r = 0.0f;
        #pragma unroll
        for (int i = lane; i < BATCH; i += 32)
            r += __ldcg(&g_nll[i]);
        #pragma unroll
        for (int off = 16; off; off >>= 1)
            r += __shfl_xor_sync(0xffffffffu, r, off);
        if (lane == 0) {
            out[0] = r * (1.0f / (float)BATCH);
            g_count = 0;   // reset for next graph replay
        }
    }
}

extern "C" void kernel_launch(void* const* d_in, const int* in_sizes, int n_in,
                              void* d_out, int out_size)
{
    const float* emissions   = (const float*)d_in[0];
    const float* transitions = (const float*)d_in[1];
    const int*   tags        = (const int*)d_in[2];
    const int*   mask        = (const int*)d_in[3];
    float*       out         = (float*)d_out;

    crf_fused_kernel<<<BATCH, 32>>>(emissions, transitions, tags, mask, out);
}